// round 1
// baseline (speedup 1.0000x reference)
#include <cuda_runtime.h>
#include <cuda_bf16.h>
#include <mma.h>

using namespace nvcuda;

// Problem constants
#define B_IMG   16
#define NW_     64
#define BW_     1024          // B_IMG * NW_
#define N_      64            // tokens per window
#define DIM_    512
#define NH_     16
#define HD_     32
#define TD3_    1536          // 3*DIM
#define SCALE_  0.17677669529663687f   // HD^-0.5

// Scratch: qkv [3][BW*NH][N][HD], attention output [BW][N][DIM]
__device__ float g_qkv[3ull * BW_ * NH_ * N_ * HD_];     // 100,663,296 floats
__device__ float g_att[(size_t)BW_ * N_ * DIM_];         //  33,554,432 floats

#define QKV_STRIDE (1ull * BW_ * NH_ * N_ * HD_)         // 33,554,432

// ---------------------------------------------------------------------------
// GEMM tiling: 128x128 block tile, BK=32, 256 threads (8 warps, 32x64/warp)
// ---------------------------------------------------------------------------
#define BM 128
#define BN 128
#define BK 32
#define LDT 36     // smem tile row stride (32 + 4 pad)
#define LDC 132    // smem epilogue row stride (128 + 4 pad)
#define GEMM_SMEM_BYTES (BM * LDC * 4)   // 67584 (>= (BM+BN)*LDT*4 = 36864)

template <typename FragT>
__device__ __forceinline__ void to_tf32(FragT& f) {
#pragma unroll
    for (int e = 0; e < f.num_elements; e++) f.x[e] = wmma::__float_to_tf32(f.x[e]);
}

// Core GEMM: C[m, j] = sum_k A[m, k] * W[j, k]   (A row-major MxK, W row-major NxK)
// Results left in smem sC[BM][LDC]; caller-provided epilogue via lambda-like macro
// is avoided -> two explicit kernels share this inline body.
__device__ __forceinline__ void gemm_body(const float* __restrict__ A,
                                          const float* __restrict__ W,
                                          int K, int m0, int j0,
                                          float* sA, float* sB, float* sC) {
    int tid  = threadIdx.x;
    int warp = tid >> 5;
    int wm   = warp & 3;   // row group (32 rows)
    int wn   = warp >> 2;  // col group (64 cols)

    wmma::fragment<wmma::accumulator, 16, 16, 8, float> acc[2][4];
#pragma unroll
    for (int i = 0; i < 2; i++)
#pragma unroll
        for (int j = 0; j < 4; j++) wmma::fill_fragment(acc[i][j], 0.0f);

    for (int kt = 0; kt < K; kt += BK) {
        // stage A tile [BM][BK] and B tile [BN][BK]
#pragma unroll
        for (int i = tid; i < BM * (BK / 4); i += 256) {
            int r = i >> 3, c4 = i & 7;
            *(float4*)&sA[r * LDT + c4 * 4] =
                *(const float4*)&A[(size_t)(m0 + r) * K + kt + c4 * 4];
        }
#pragma unroll
        for (int i = tid; i < BN * (BK / 4); i += 256) {
            int r = i >> 3, c4 = i & 7;
            *(float4*)&sB[r * LDT + c4 * 4] =
                *(const float4*)&W[(size_t)(j0 + r) * K + kt + c4 * 4];
        }
        __syncthreads();

#pragma unroll
        for (int kk = 0; kk < BK; kk += 8) {
            wmma::fragment<wmma::matrix_a, 16, 16, 8, wmma::precision::tf32, wmma::row_major> af[2];
            wmma::fragment<wmma::matrix_b, 16, 16, 8, wmma::precision::tf32, wmma::col_major> bf[4];
#pragma unroll
            for (int i = 0; i < 2; i++) {
                wmma::load_matrix_sync(af[i], &sA[(wm * 32 + i * 16) * LDT + kk], LDT);
                to_tf32(af[i]);
            }
#pragma unroll
            for (int j = 0; j < 4; j++) {
                wmma::load_matrix_sync(bf[j], &sB[(wn * 64 + j * 16) * LDT + kk], LDT);
                to_tf32(bf[j]);
            }
#pragma unroll
            for (int i = 0; i < 2; i++)
#pragma unroll
                for (int j = 0; j < 4; j++)
                    wmma::mma_sync(acc[i][j], af[i], bf[j], acc[i][j]);
        }
        __syncthreads();
    }

    // dump accumulators to smem epilogue buffer (overlays sA/sB)
#pragma unroll
    for (int i = 0; i < 2; i++)
#pragma unroll
        for (int j = 0; j < 4; j++)
            wmma::store_matrix_sync(&sC[(wm * 32 + i * 16) * LDC + wn * 64 + j * 16],
                                    acc[i][j], LDC, wmma::mem_row_major);
    __syncthreads();
}

// K1: QKV projection. C = x @ qkv_w^T + qkv_b; scatter to g_qkv, q pre-scaled.
extern "C" __global__ void __launch_bounds__(256)
qkv_kernel(const float* __restrict__ x, const float* __restrict__ w,
           const float* __restrict__ bias) {
    extern __shared__ float smem[];
    float* sA = smem;
    float* sB = smem + BM * LDT;
    float* sC = smem;

    int m0 = blockIdx.x * BM;
    int j0 = blockIdx.y * BN;
    gemm_body(x, w, DIM_, m0, j0, sA, sB, sC);

    int tid = threadIdx.x;
    for (int i = tid; i < BM * BN; i += 256) {
        int r = i >> 7, c = i & 127;
        int m = m0 + r;
        int j = j0 + c;
        float v = sC[r * LDC + c] + bias[j];
        int which = j >> 9;           // 0=q 1=k 2=v
        int h     = (j >> 5) & 15;
        int d     = j & 31;
        if (which == 0) v *= SCALE_;
        int wdw = m >> 6, n = m & 63;
        size_t dst = (size_t)which * QKV_STRIDE
                   + ((size_t)(wdw * NH_ + h) * N_ + n) * HD_ + d;
        g_qkv[dst] = v;
    }
}

// K3: projection. out = g_att @ proj_w^T + proj_b
extern "C" __global__ void __launch_bounds__(256)
proj_kernel(const float* __restrict__ w, const float* __restrict__ bias,
            float* __restrict__ out) {
    extern __shared__ float smem[];
    float* sA = smem;
    float* sB = smem + BM * LDT;
    float* sC = smem;

    int m0 = blockIdx.x * BM;
    int j0 = blockIdx.y * BN;
    gemm_body(g_att, w, DIM_, m0, j0, sA, sB, sC);

    int tid = threadIdx.x;
    for (int i = tid; i < BM * BN; i += 256) {
        int r = i >> 7, c = i & 127;
        out[(size_t)(m0 + r) * DIM_ + j0 + c] = sC[r * LDC + c] + bias[j0 + c];
    }
}

// ---------------------------------------------------------------------------
// K2: attention per (window, head). 128 threads (4 warps).
// ---------------------------------------------------------------------------
#define LQ 36
#define LS 68

extern "C" __global__ void __launch_bounds__(128)
attn_kernel(const float* __restrict__ mask, const float* __restrict__ table,
            const int* __restrict__ ridx) {
    __shared__ float sQ[N_][LQ];
    __shared__ float sK[N_][LQ];
    __shared__ float sV[N_][LQ];
    __shared__ float sS[N_][LS];

    int bwh = blockIdx.x;
    int wdw = bwh >> 4;
    int h   = bwh & 15;
    int tid = threadIdx.x;
    int warp = tid >> 5;

    const float* q = g_qkv + (size_t)bwh * (N_ * HD_);
    const float* k = q + QKV_STRIDE;
    const float* v = k + QKV_STRIDE;

    // stage Q, K, V (each 64x32 fp32 -> 512 float4 each)
    for (int i = tid; i < 512; i += 128) {
        int n = i >> 3, c4 = i & 7;
        *(float4*)&sQ[n][c4 * 4] = *(const float4*)&q[n * HD_ + c4 * 4];
        *(float4*)&sK[n][c4 * 4] = *(const float4*)&k[n * HD_ + c4 * 4];
        *(float4*)&sV[n][c4 * 4] = *(const float4*)&v[n * HD_ + c4 * 4];
    }
    __syncthreads();

    // scores: S = Qs @ K^T; warp handles 16-row band, all 64 cols
    {
        wmma::fragment<wmma::accumulator, 16, 16, 8, float> acc[4];
#pragma unroll
        for (int j = 0; j < 4; j++) wmma::fill_fragment(acc[j], 0.0f);
#pragma unroll
        for (int kk = 0; kk < HD_; kk += 8) {
            wmma::fragment<wmma::matrix_a, 16, 16, 8, wmma::precision::tf32, wmma::row_major> af;
            wmma::load_matrix_sync(af, &sQ[warp * 16][kk], LQ);
            to_tf32(af);
#pragma unroll
            for (int j = 0; j < 4; j++) {
                wmma::fragment<wmma::matrix_b, 16, 16, 8, wmma::precision::tf32, wmma::col_major> bf;
                wmma::load_matrix_sync(bf, &sK[j * 16][kk], LQ);
                to_tf32(bf);
                wmma::mma_sync(acc[j], af, bf, acc[j]);
            }
        }
#pragma unroll
        for (int j = 0; j < 4; j++)
            wmma::store_matrix_sync(&sS[warp * 16][j * 16], acc[j], LS, wmma::mem_row_major);
    }
    __syncthreads();

    // bias + mask + softmax: 2 threads per row (32 cols each)
    {
        int r    = tid >> 1;
        int base = (tid & 1) * 32;
        const float* mrow = mask + ((size_t)(wdw & 63) * N_ + r) * N_;
        const int*   irow = ridx + r * N_;

        float mx = -1e30f;
#pragma unroll
        for (int c = 0; c < 32; c++) {
            int col = base + c;
            float val = sS[r][col] + table[irow[col] * NH_ + h] + mrow[col];
            sS[r][col] = val;
            mx = fmaxf(mx, val);
        }
        mx = fmaxf(mx, __shfl_xor_sync(0xffffffffu, mx, 1));
        float sum = 0.0f;
#pragma unroll
        for (int c = 0; c < 32; c++) {
            int col = base + c;
            float e = __expf(sS[r][col] - mx);
            sS[r][col] = e;
            sum += e;
        }
        sum += __shfl_xor_sync(0xffffffffu, sum, 1);
        float inv = 1.0f / sum;
#pragma unroll
        for (int c = 0; c < 32; c++) sS[r][base + c] *= inv;
    }
    __syncthreads();

    // O = P @ V; warp handles 16-row band x 32 cols
    {
        wmma::fragment<wmma::accumulator, 16, 16, 8, float> acc[2];
        wmma::fill_fragment(acc[0], 0.0f);
        wmma::fill_fragment(acc[1], 0.0f);
#pragma unroll
        for (int kk = 0; kk < N_; kk += 8) {
            wmma::fragment<wmma::matrix_a, 16, 16, 8, wmma::precision::tf32, wmma::row_major> af;
            wmma::load_matrix_sync(af, &sS[warp * 16][kk], LS);
            to_tf32(af);
#pragma unroll
            for (int j = 0; j < 2; j++) {
                wmma::fragment<wmma::matrix_b, 16, 16, 8, wmma::precision::tf32, wmma::row_major> bf;
                wmma::load_matrix_sync(bf, &sV[kk][j * 16], LQ);
                to_tf32(bf);
                wmma::mma_sync(acc[j], af, bf, acc[j]);
            }
        }
        float* o = g_att + ((size_t)(wdw * N_ + warp * 16)) * DIM_ + h * HD_;
#pragma unroll
        for (int j = 0; j < 2; j++)
            wmma::store_matrix_sync(o + j * 16, acc[j], DIM_, wmma::mem_row_major);
    }
}

// ---------------------------------------------------------------------------
extern "C" void kernel_launch(void* const* d_in, const int* in_sizes, int n_in,
                              void* d_out, int out_size) {
    const float* x      = (const float*)d_in[0];
    const float* mask   = (const float*)d_in[1];
    const float* qkv_w  = (const float*)d_in[2];
    const float* qkv_b  = (const float*)d_in[3];
    const float* table  = (const float*)d_in[4];
    const float* proj_w = (const float*)d_in[5];
    const float* proj_b = (const float*)d_in[6];
    const int*   ridx   = (const int*)d_in[7];
    float* out = (float*)d_out;

    cudaFuncSetAttribute(qkv_kernel, cudaFuncAttributeMaxDynamicSharedMemorySize, GEMM_SMEM_BYTES);
    cudaFuncSetAttribute(proj_kernel, cudaFuncAttributeMaxDynamicSharedMemorySize, GEMM_SMEM_BYTES);

    // K1: QKV projection  (65536 x 1536 x 512)
    qkv_kernel<<<dim3((BW_ * N_) / BM, TD3_ / BN), 256, GEMM_SMEM_BYTES>>>(x, qkv_w, qkv_b);
    // K2: windowed attention, one block per (window, head)
    attn_kernel<<<BW_ * NH_, 128>>>(mask, table, ridx);
    // K3: output projection (65536 x 512 x 512)
    proj_kernel<<<dim3((BW_ * N_) / BM, DIM_ / BN), 256, GEMM_SMEM_BYTES>>>(proj_w, proj_b, out);
}

// round 5
// speedup vs baseline: 1.8428x; 1.8428x over previous
#include <cuda_runtime.h>
#include <cuda_bf16.h>
#include <mma.h>
#include <cstdint>

using namespace nvcuda;

// Problem constants
#define B_IMG   16
#define NW_     64
#define BW_     1024          // B_IMG * NW_
#define N_      64            // tokens per window
#define DIM_    512
#define NH_     16
#define HD_     32
#define TD3_    1536          // 3*DIM
#define SCALE_  0.17677669529663687f   // HD^-0.5

// Scratch: qkv [3][BW*NH][N][HD], attention output [BW][N][DIM]
__device__ float g_qkv[3ull * BW_ * NH_ * N_ * HD_];
__device__ float g_att[(size_t)BW_ * N_ * DIM_];

#define QKV_STRIDE (1ull * BW_ * NH_ * N_ * HD_)         // 33,554,432

// ---------------------------------------------------------------------------
// GEMM tiling: 128x128 block tile, BK=32, 256 threads (8 warps, 32x64/warp),
// cp.async double-buffered, bias pre-loaded into accumulators, direct global
// fragment stores (no smem epilogue).
// ---------------------------------------------------------------------------
#define BM 128
#define BN 128
#define BK 32
#define LDT 36                       // tile row stride (32 + 4 pad floats)
#define STG_FLOATS ((BM + BN) * LDT) // 9216 floats per stage
#define BIAS_OFF   (2 * STG_FLOATS)  // 18432
#define LDBIAS 132
#define GEMM_SMEM_BYTES ((BIAS_OFF + 16 * LDBIAS) * 4)   // 82176 bytes

__device__ __forceinline__ void cp_async16(float* smem_dst, const float* gsrc) {
    unsigned int s = (unsigned int)__cvta_generic_to_shared(smem_dst);
    asm volatile("cp.async.cg.shared.global [%0], [%1], 16;\n" :: "r"(s), "l"(gsrc));
}
__device__ __forceinline__ void cp_commit() {
    asm volatile("cp.async.commit_group;\n" ::);
}
__device__ __forceinline__ void cp_wait0() {
    asm volatile("cp.async.wait_group 0;\n" ::);
}

template <typename FragT>
__device__ __forceinline__ void to_tf32(FragT& f) {
#pragma unroll
    for (int e = 0; e < f.num_elements; e++) f.x[e] = wmma::__float_to_tf32(f.x[e]);
}

// Issue one stage of cp.async loads: A[BM][BK] from (m0, kt), B[BN][BK] from (j0, kt)
__device__ __forceinline__ void issue_stage(const float* __restrict__ A,
                                            const float* __restrict__ W,
                                            int K, int m0, int j0, int kt,
                                            float* sA, float* sB, int tid) {
#pragma unroll
    for (int u = 0; u < 4; u++) {
        int i  = tid + u * 256;          // 1024 float4 for A
        int r  = i >> 3, c4 = i & 7;
        cp_async16(&sA[r * LDT + c4 * 4], &A[(size_t)(m0 + r) * K + kt + c4 * 4]);
    }
#pragma unroll
    for (int u = 0; u < 4; u++) {
        int i  = tid + u * 256;
        int r  = i >> 3, c4 = i & 7;
        cp_async16(&sB[r * LDT + c4 * 4], &W[(size_t)(j0 + r) * K + kt + c4 * 4]);
    }
}

// Core pipelined GEMM. Accumulators arrive pre-initialized (bias); results
// stay in acc for the caller's direct global store.
__device__ __forceinline__ void gemm_main(const float* __restrict__ A,
                                          const float* __restrict__ W,
                                          int K, int m0, int j0,
                                          float* smem, int tid, int wm, int wn,
                                          wmma::fragment<wmma::accumulator, 16, 16, 8, float> (&acc)[2][4]) {
    float* sA0 = smem;
    float* sB0 = smem + BM * LDT;
    float* sA1 = smem + STG_FLOATS;
    float* sB1 = sA1 + BM * LDT;

    issue_stage(A, W, K, m0, j0, 0, sA0, sB0, tid);
    cp_commit();

    const int T = K / BK;
    int buf = 0;
    for (int t = 0; t < T; t++) {
        cp_wait0();
        __syncthreads();
        if (t + 1 < T) {
            issue_stage(A, W, K, m0, j0, (t + 1) * BK,
                        buf ? sA0 : sA1, buf ? sB0 : sB1, tid);
            cp_commit();
        }
        float* sA = buf ? sA1 : sA0;
        float* sB = buf ? sB1 : sB0;
#pragma unroll
        for (int kk = 0; kk < BK; kk += 8) {
            wmma::fragment<wmma::matrix_a, 16, 16, 8, wmma::precision::tf32, wmma::row_major> af[2];
            wmma::fragment<wmma::matrix_b, 16, 16, 8, wmma::precision::tf32, wmma::col_major> bf[4];
#pragma unroll
            for (int i = 0; i < 2; i++) {
                wmma::load_matrix_sync(af[i], &sA[(wm * 32 + i * 16) * LDT + kk], LDT);
                to_tf32(af[i]);
            }
#pragma unroll
            for (int j = 0; j < 4; j++) {
                wmma::load_matrix_sync(bf[j], &sB[(wn * 64 + j * 16) * LDT + kk], LDT);
                to_tf32(bf[j]);
            }
#pragma unroll
            for (int i = 0; i < 2; i++)
#pragma unroll
                for (int j = 0; j < 4; j++)
                    wmma::mma_sync(acc[i][j], af[i], bf[j], acc[i][j]);
        }
        buf ^= 1;
    }
}

// Fill 16-row replicated bias tile and load it into accumulators.
__device__ __forceinline__ void init_acc_bias(const float* __restrict__ bias, int j0,
                                              float* sBias, int tid, int wn,
                                              wmma::fragment<wmma::accumulator, 16, 16, 8, float> (&acc)[2][4]) {
    for (int i = tid; i < 16 * BN; i += 256) {
        int r = i >> 7, c = i & 127;
        sBias[r * LDBIAS + c] = bias[j0 + c];
    }
    __syncthreads();
#pragma unroll
    for (int j = 0; j < 4; j++) {
        wmma::load_matrix_sync(acc[0][j], &sBias[wn * 64 + j * 16], LDBIAS, wmma::mem_row_major);
        acc[1][j] = acc[0][j];
    }
    __syncthreads();
}

// K1: QKV projection. out = x @ qkv_w^T + qkv_b; scatter to g_qkv; q pre-scaled.
extern "C" __global__ void __launch_bounds__(256, 2)
qkv_kernel(const float* __restrict__ x, const float* __restrict__ w,
           const float* __restrict__ bias) {
    extern __shared__ float smem[];
    int tid  = threadIdx.x;
    int warp = tid >> 5;
    int wm   = warp & 3;
    int wn   = warp >> 2;

    int j0 = blockIdx.x * BN;      // fast dim = columns -> A reuse in L2
    int m0 = blockIdx.y * BM;
    int which = j0 >> 9;           // 0=q 1=k 2=v (constant per block)

    wmma::fragment<wmma::accumulator, 16, 16, 8, float> acc[2][4];
    init_acc_bias(bias, j0, smem + BIAS_OFF, tid, wn, acc);
    gemm_main(x, w, DIM_, m0, j0, smem, tid, wm, wn, acc);

    // scale (q only) and scatter fragments directly to g_qkv
#pragma unroll
    for (int i = 0; i < 2; i++)
#pragma unroll
        for (int j = 0; j < 4; j++) {
            if (which == 0) {
#pragma unroll
                for (int e = 0; e < acc[i][j].num_elements; e++) acc[i][j].x[e] *= SCALE_;
            }
            int row = m0 + wm * 32 + i * 16;        // 16-aligned -> single window
            int col = j0 + wn * 64 + j * 16;        // 16-aligned -> single head
            int wdw = row >> 6, n0 = row & 63;
            int h   = (col >> 5) & 15, d0 = col & 31;
            float* dst = g_qkv + (size_t)which * QKV_STRIDE
                       + ((size_t)(wdw * NH_ + h) * N_ + n0) * HD_ + d0;
            wmma::store_matrix_sync(dst, acc[i][j], HD_, wmma::mem_row_major);
        }
}

// K3: projection. out = g_att @ proj_w^T + proj_b
extern "C" __global__ void __launch_bounds__(256, 2)
proj_kernel(const float* __restrict__ w, const float* __restrict__ bias,
            float* __restrict__ out) {
    extern __shared__ float smem[];
    int tid  = threadIdx.x;
    int warp = tid >> 5;
    int wm   = warp & 3;
    int wn   = warp >> 2;

    int j0 = blockIdx.x * BN;
    int m0 = blockIdx.y * BM;

    wmma::fragment<wmma::accumulator, 16, 16, 8, float> acc[2][4];
    init_acc_bias(bias, j0, smem + BIAS_OFF, tid, wn, acc);
    gemm_main(g_att, w, DIM_, m0, j0, smem, tid, wm, wn, acc);

#pragma unroll
    for (int i = 0; i < 2; i++)
#pragma unroll
        for (int j = 0; j < 4; j++) {
            int row = m0 + wm * 32 + i * 16;
            int col = j0 + wn * 64 + j * 16;
            wmma::store_matrix_sync(out + (size_t)row * DIM_ + col, acc[i][j],
                                    DIM_, wmma::mem_row_major);
        }
}

// ---------------------------------------------------------------------------
// K2: attention per (window, head). 128 threads (4 warps).
// ---------------------------------------------------------------------------
#define LQ 36
#define LS 68

extern "C" __global__ void __launch_bounds__(128)
attn_kernel(const float* __restrict__ mask, const float* __restrict__ table,
            const int* __restrict__ ridx) {
    __shared__ float sQ[N_][LQ];
    __shared__ float sK[N_][LQ];
    __shared__ float sV[N_][LQ];
    __shared__ float sS[N_][LS];

    int bwh = blockIdx.x;
    int wdw = bwh >> 4;
    int h   = bwh & 15;
    int tid = threadIdx.x;
    int warp = tid >> 5;

    const float* q = g_qkv + (size_t)bwh * (N_ * HD_);
    const float* k = q + QKV_STRIDE;
    const float* v = k + QKV_STRIDE;

    for (int i = tid; i < 512; i += 128) {
        int n = i >> 3, c4 = i & 7;
        *(float4*)&sQ[n][c4 * 4] = *(const float4*)&q[n * HD_ + c4 * 4];
        *(float4*)&sK[n][c4 * 4] = *(const float4*)&k[n * HD_ + c4 * 4];
        *(float4*)&sV[n][c4 * 4] = *(const float4*)&v[n * HD_ + c4 * 4];
    }
    __syncthreads();

    // scores: S = Qs @ K^T
    {
        wmma::fragment<wmma::accumulator, 16, 16, 8, float> acc[4];
#pragma unroll
        for (int j = 0; j < 4; j++) wmma::fill_fragment(acc[j], 0.0f);
#pragma unroll
        for (int kk = 0; kk < HD_; kk += 8) {
            wmma::fragment<wmma::matrix_a, 16, 16, 8, wmma::precision::tf32, wmma::row_major> af;
            wmma::load_matrix_sync(af, &sQ[warp * 16][kk], LQ);
            to_tf32(af);
#pragma unroll
            for (int j = 0; j < 4; j++) {
                wmma::fragment<wmma::matrix_b, 16, 16, 8, wmma::precision::tf32, wmma::col_major> bf;
                wmma::load_matrix_sync(bf, &sK[j * 16][kk], LQ);
                to_tf32(bf);
                wmma::mma_sync(acc[j], af, bf, acc[j]);
            }
        }
#pragma unroll
        for (int j = 0; j < 4; j++)
            wmma::store_matrix_sync(&sS[warp * 16][j * 16], acc[j], LS, wmma::mem_row_major);
    }
    __syncthreads();

    // bias + mask + softmax: 2 threads per row (32 cols each)
    {
        int r    = tid >> 1;
        int base = (tid & 1) * 32;
        const float* mrow = mask + ((size_t)(wdw & 63) * N_ + r) * N_;
        const int*   irow = ridx + r * N_;

        float mx = -1e30f;
#pragma unroll
        for (int c = 0; c < 32; c++) {
            int col = base + c;
            float val = sS[r][col] + table[irow[col] * NH_ + h] + mrow[col];
            sS[r][col] = val;
            mx = fmaxf(mx, val);
        }
        mx = fmaxf(mx, __shfl_xor_sync(0xffffffffu, mx, 1));
        float sum = 0.0f;
#pragma unroll
        for (int c = 0; c < 32; c++) {
            int col = base + c;
            float e = __expf(sS[r][col] - mx);
            sS[r][col] = e;
            sum += e;
        }
        sum += __shfl_xor_sync(0xffffffffu, sum, 1);
        float inv = 1.0f / sum;
#pragma unroll
        for (int c = 0; c < 32; c++) sS[r][base + c] *= inv;
    }
    __syncthreads();

    // O = P @ V
    {
        wmma::fragment<wmma::accumulator, 16, 16, 8, float> acc[2];
        wmma::fill_fragment(acc[0], 0.0f);
        wmma::fill_fragment(acc[1], 0.0f);
#pragma unroll
        for (int kk = 0; kk < N_; kk += 8) {
            wmma::fragment<wmma::matrix_a, 16, 16, 8, wmma::precision::tf32, wmma::row_major> af;
            wmma::load_matrix_sync(af, &sS[warp * 16][kk], LS);
            to_tf32(af);
#pragma unroll
            for (int j = 0; j < 2; j++) {
                wmma::fragment<wmma::matrix_b, 16, 16, 8, wmma::precision::tf32, wmma::row_major> bf;
                wmma::load_matrix_sync(bf, &sV[kk][j * 16], LQ);
                to_tf32(bf);
                wmma::mma_sync(acc[j], af, bf, acc[j]);
            }
        }
        float* o = g_att + ((size_t)(wdw * N_ + warp * 16)) * DIM_ + h * HD_;
#pragma unroll
        for (int j = 0; j < 2; j++)
            wmma::store_matrix_sync(o + j * 16, acc[j], DIM_, wmma::mem_row_major);
    }
}

// ---------------------------------------------------------------------------
extern "C" void kernel_launch(void* const* d_in, const int* in_sizes, int n_in,
                              void* d_out, int out_size) {
    const float* x      = (const float*)d_in[0];
    const float* mask   = (const float*)d_in[1];
    const float* qkv_w  = (const float*)d_in[2];
    const float* qkv_b  = (const float*)d_in[3];
    const float* table  = (const float*)d_in[4];
    const float* proj_w = (const float*)d_in[5];
    const float* proj_b = (const float*)d_in[6];
    const int*   ridx   = (const int*)d_in[7];
    float* out = (float*)d_out;

    cudaFuncSetAttribute(qkv_kernel, cudaFuncAttributeMaxDynamicSharedMemorySize, GEMM_SMEM_BYTES);
    cudaFuncSetAttribute(proj_kernel, cudaFuncAttributeMaxDynamicSharedMemorySize, GEMM_SMEM_BYTES);

    // K1: QKV projection (65536 x 1536 x 512); col tiles fast for A L2 reuse
    qkv_kernel<<<dim3(TD3_ / BN, (BW_ * N_) / BM), 256, GEMM_SMEM_BYTES>>>(x, qkv_w, qkv_b);
    // K2: windowed attention, one block per (window, head)
    attn_kernel<<<BW_ * NH_, 128>>>(mask, table, ridx);
    // K3: output projection (65536 x 512 x 512)
    proj_kernel<<<dim3(DIM_ / BN, (BW_ * N_) / BM), 256, GEMM_SMEM_BYTES>>>(proj_w, proj_b, out);
}

// round 7
// speedup vs baseline: 2.3898x; 1.2969x over previous
#include <cuda_runtime.h>
#include <cuda_bf16.h>
#include <mma.h>
#include <cstdint>

using namespace nvcuda;

// Problem constants
#define B_IMG   16
#define NW_     64
#define BW_     1024          // B_IMG * NW_
#define N_      64            // tokens per window
#define DIM_    512
#define NH_     16
#define HD_     32
#define TD3_    1536          // 3*DIM
#define SCALE_  0.17677669529663687f   // HD^-0.5

// Scratch
__device__ float g_qkv[3ull * BW_ * NH_ * N_ * HD_];
__device__ float g_att[(size_t)BW_ * N_ * DIM_];
__device__ float g_bias[NH_ * N_ * N_];          // per-head rel-pos bias, precomputed

#define QKV_STRIDE (1ull * BW_ * NH_ * N_ * HD_)

// ---------------------------------------------------------------------------
// GEMM: 128x128 block tile, BK=32, 128 threads (4 warps, 64x64 per warp),
// 3-stage cp.async pipeline, bias preloaded into accumulators, direct global
// fragment stores.
// ---------------------------------------------------------------------------
#define BM 128
#define BN 128
#define BK 32
#define LDT 36                        // stage row stride (32 + 4 pad)
#define STG_FLOATS ((BM + BN) * LDT)  // 9216 floats per stage
#define NSTAGE 3
#define LDBIAS 132
#define GEMM_SMEM_BYTES (NSTAGE * STG_FLOATS * 4)   // 110592 bytes

__device__ __forceinline__ void cp_async16(float* smem_dst, const float* gsrc) {
    unsigned int s = (unsigned int)__cvta_generic_to_shared(smem_dst);
    asm volatile("cp.async.cg.shared.global [%0], [%1], 16;\n" :: "r"(s), "l"(gsrc));
}
__device__ __forceinline__ void cp_commit() {
    asm volatile("cp.async.commit_group;\n" ::);
}
__device__ __forceinline__ void cp_wait1() {
    asm volatile("cp.async.wait_group 1;\n" ::);
}

template <typename FragT>
__device__ __forceinline__ void to_tf32(FragT& f) {
#pragma unroll
    for (int e = 0; e < f.num_elements; e++) f.x[e] = wmma::__float_to_tf32(f.x[e]);
}

// Issue one stage: A[BM][BK] from (m0, kt), B[BN][BK] from (j0, kt). 128 threads.
__device__ __forceinline__ void issue_stage(const float* __restrict__ A,
                                            const float* __restrict__ W,
                                            int K, int m0, int j0, int kt,
                                            float* stg, int tid) {
    float* sA = stg;
    float* sB = stg + BM * LDT;
#pragma unroll
    for (int u = 0; u < 8; u++) {
        int i = tid + u * 128;           // 1024 float4 for A
        int r = i >> 3, c4 = i & 7;
        cp_async16(&sA[r * LDT + c4 * 4], &A[(size_t)(m0 + r) * K + kt + c4 * 4]);
    }
#pragma unroll
    for (int u = 0; u < 8; u++) {
        int i = tid + u * 128;
        int r = i >> 3, c4 = i & 7;
        cp_async16(&sB[r * LDT + c4 * 4], &W[(size_t)(j0 + r) * K + kt + c4 * 4]);
    }
}

// Core: bias -> acc, 3-stage pipelined mainloop. Results remain in acc.
__device__ __forceinline__ void gemm_core(const float* __restrict__ A,
                                          const float* __restrict__ W,
                                          const float* __restrict__ bias,
                                          int K, int m0, int j0,
                                          float* smem, int tid, int wm, int wn,
                                          wmma::fragment<wmma::accumulator, 16, 16, 8, float> (&acc)[4][4]) {
    // ---- bias preload (overlays stage 0 smem) ----
    for (int i = tid; i < 16 * BN; i += 128) {
        int r = i >> 7, c = i & 127;
        smem[r * LDBIAS + c] = bias[j0 + c];
    }
    __syncthreads();
#pragma unroll
    for (int j = 0; j < 4; j++) {
        wmma::load_matrix_sync(acc[0][j], &smem[wn * 64 + j * 16], LDBIAS, wmma::mem_row_major);
#pragma unroll
        for (int i = 1; i < 4; i++) acc[i][j] = acc[0][j];
    }
    __syncthreads();

    // ---- pipeline prologue: stages 0,1 ----
    const int T = K / BK;
    issue_stage(A, W, K, m0, j0, 0, smem, tid);
    cp_commit();
    issue_stage(A, W, K, m0, j0, BK, smem + STG_FLOATS, tid);
    cp_commit();

    int slot = 0;
    for (int t = 0; t < T; t++) {
        cp_wait1();                 // stage t resident (1 newer may be in flight)
        __syncthreads();
        // refill slot (t+2)%NSTAGE
        if (t + 2 < T) {
            issue_stage(A, W, K, m0, j0, (t + 2) * BK,
                        smem + ((slot + 2) % NSTAGE) * STG_FLOATS, tid);
        }
        cp_commit();                // always commit to keep group accounting exact

        float* sA = smem + slot * STG_FLOATS;
        float* sB = sA + BM * LDT;
#pragma unroll
        for (int kk = 0; kk < BK; kk += 8) {
            wmma::fragment<wmma::matrix_a, 16, 16, 8, wmma::precision::tf32, wmma::row_major> af[4];
            wmma::fragment<wmma::matrix_b, 16, 16, 8, wmma::precision::tf32, wmma::col_major> bf[4];
#pragma unroll
            for (int i = 0; i < 4; i++) {
                wmma::load_matrix_sync(af[i], &sA[(wm * 64 + i * 16) * LDT + kk], LDT);
                to_tf32(af[i]);
            }
#pragma unroll
            for (int j = 0; j < 4; j++) {
                wmma::load_matrix_sync(bf[j], &sB[(wn * 64 + j * 16) * LDT + kk], LDT);
                to_tf32(bf[j]);
            }
#pragma unroll
            for (int i = 0; i < 4; i++)
#pragma unroll
                for (int j = 0; j < 4; j++)
                    wmma::mma_sync(acc[i][j], af[i], bf[j], acc[i][j]);
        }
        slot = (slot + 1) % NSTAGE;
    }
}

// K1: QKV projection; scatter to g_qkv; q pre-scaled.
extern "C" __global__ void __launch_bounds__(128)
qkv_kernel(const float* __restrict__ x, const float* __restrict__ w,
           const float* __restrict__ bias) {
    extern __shared__ float smem[];
    int tid  = threadIdx.x;
    int warp = tid >> 5;
    int wm   = warp & 1;       // row half (64 rows)
    int wn   = warp >> 1;      // col half (64 cols)

    int j0 = blockIdx.x * BN;  // fast dim = columns -> A reuse in L2
    int m0 = blockIdx.y * BM;
    int which = j0 >> 9;       // 0=q 1=k 2=v (block-constant: BN=128 divides 512)

    wmma::fragment<wmma::accumulator, 16, 16, 8, float> acc[4][4];
    gemm_core(x, w, bias, DIM_, m0, j0, smem, tid, wm, wn, acc);

#pragma unroll
    for (int i = 0; i < 4; i++)
#pragma unroll
        for (int j = 0; j < 4; j++) {
            if (which == 0) {
#pragma unroll
                for (int e = 0; e < acc[i][j].num_elements; e++) acc[i][j].x[e] *= SCALE_;
            }
            int row = m0 + wm * 64 + i * 16;   // 16-aligned -> single window
            int col = j0 + wn * 64 + j * 16;   // 16-aligned -> single head
            int wdw = row >> 6, n0 = row & 63;
            int h   = (col >> 5) & 15, d0 = col & 31;
            float* dst = g_qkv + (size_t)which * QKV_STRIDE
                       + ((size_t)(wdw * NH_ + h) * N_ + n0) * HD_ + d0;
            wmma::store_matrix_sync(dst, acc[i][j], HD_, wmma::mem_row_major);
        }
}

// K3: output projection
extern "C" __global__ void __launch_bounds__(128)
proj_kernel(const float* __restrict__ w, const float* __restrict__ bias,
            float* __restrict__ out) {
    extern __shared__ float smem[];
    int tid  = threadIdx.x;
    int warp = tid >> 5;
    int wm   = warp & 1;
    int wn   = warp >> 1;

    int j0 = blockIdx.x * BN;
    int m0 = blockIdx.y * BM;

    wmma::fragment<wmma::accumulator, 16, 16, 8, float> acc[4][4];
    gemm_core(g_att, w, bias, DIM_, m0, j0, smem, tid, wm, wn, acc);

#pragma unroll
    for (int i = 0; i < 4; i++)
#pragma unroll
        for (int j = 0; j < 4; j++) {
            int row = m0 + wm * 64 + i * 16;
            int col = j0 + wn * 64 + j * 16;
            wmma::store_matrix_sync(out + (size_t)row * DIM_ + col, acc[i][j],
                                    DIM_, wmma::mem_row_major);
        }
}

// ---------------------------------------------------------------------------
// K0: expand rel-pos bias table to per-head [NH][N][N]
// ---------------------------------------------------------------------------
extern "C" __global__ void __launch_bounds__(256)
bias_kernel(const float* __restrict__ table, const int* __restrict__ ridx) {
    int i = blockIdx.x * 256 + threadIdx.x;     // 0 .. NH*N*N-1
    if (i < NH_ * N_ * N_) {
        int h  = i >> 12;
        int rc = i & 4095;
        g_bias[i] = table[ridx[rc] * NH_ + h];
    }
}

// ---------------------------------------------------------------------------
// K2: attention per (window, head). 128 threads (4 warps).
// ---------------------------------------------------------------------------
#define LQ 36
#define LS 68

extern "C" __global__ void __launch_bounds__(128)
attn_kernel(const float* __restrict__ mask) {
    __shared__ float sQ[N_][LQ];
    __shared__ float sK[N_][LQ];
    __shared__ float sV[N_][LQ];
    __shared__ float sS[N_][LS];

    int bwh = blockIdx.x;
    int wdw = bwh >> 4;
    int h   = bwh & 15;
    int tid = threadIdx.x;
    int warp = tid >> 5;

    const float* q = g_qkv + (size_t)bwh * (N_ * HD_);
    const float* k = q + QKV_STRIDE;
    const float* v = k + QKV_STRIDE;

    for (int i = tid; i < 512; i += 128) {
        int n = i >> 3, c4 = i & 7;
        *(float4*)&sQ[n][c4 * 4] = *(const float4*)&q[n * HD_ + c4 * 4];
        *(float4*)&sK[n][c4 * 4] = *(const float4*)&k[n * HD_ + c4 * 4];
        *(float4*)&sV[n][c4 * 4] = *(const float4*)&v[n * HD_ + c4 * 4];
    }
    __syncthreads();

    // scores: S = Qs @ K^T
    {
        wmma::fragment<wmma::accumulator, 16, 16, 8, float> acc[4];
#pragma unroll
        for (int j = 0; j < 4; j++) wmma::fill_fragment(acc[j], 0.0f);
#pragma unroll
        for (int kk = 0; kk < HD_; kk += 8) {
            wmma::fragment<wmma::matrix_a, 16, 16, 8, wmma::precision::tf32, wmma::row_major> af;
            wmma::load_matrix_sync(af, &sQ[warp * 16][kk], LQ);
            to_tf32(af);
#pragma unroll
            for (int j = 0; j < 4; j++) {
                wmma::fragment<wmma::matrix_b, 16, 16, 8, wmma::precision::tf32, wmma::col_major> bf;
                wmma::load_matrix_sync(bf, &sK[j * 16][kk], LQ);
                to_tf32(bf);
                wmma::mma_sync(acc[j], af, bf, acc[j]);
            }
        }
#pragma unroll
        for (int j = 0; j < 4; j++)
            wmma::store_matrix_sync(&sS[warp * 16][j * 16], acc[j], LS, wmma::mem_row_major);
    }
    __syncthreads();

    // bias + mask + softmax: 2 threads per row, 32 cols each, float4 vectorized
    {
        int r    = tid >> 1;
        int base = (tid & 1) * 32;
        const float4* brow = (const float4*)(g_bias + ((size_t)h * N_ + r) * N_ + base);
        const float4* mrow = (const float4*)(mask + ((size_t)(wdw & 63) * N_ + r) * N_ + base);

        float vals[32];
        float mx = -1e30f;
#pragma unroll
        for (int c4 = 0; c4 < 8; c4++) {
            float4 bv = brow[c4];
            float4 mv = mrow[c4];
            float* vp = vals + c4 * 4;
            vp[0] = sS[r][base + c4 * 4 + 0] + bv.x + mv.x;
            vp[1] = sS[r][base + c4 * 4 + 1] + bv.y + mv.y;
            vp[2] = sS[r][base + c4 * 4 + 2] + bv.z + mv.z;
            vp[3] = sS[r][base + c4 * 4 + 3] + bv.w + mv.w;
            mx = fmaxf(mx, fmaxf(fmaxf(vp[0], vp[1]), fmaxf(vp[2], vp[3])));
        }
        mx = fmaxf(mx, __shfl_xor_sync(0xffffffffu, mx, 1));
        float sum = 0.0f;
#pragma unroll
        for (int c = 0; c < 32; c++) {
            float e = __expf(vals[c] - mx);
            vals[c] = e;
            sum += e;
        }
        sum += __shfl_xor_sync(0xffffffffu, sum, 1);
        float inv = 1.0f / sum;
#pragma unroll
        for (int c = 0; c < 32; c++) sS[r][base + c] = vals[c] * inv;
    }
    __syncthreads();

    // O = P @ V
    {
        wmma::fragment<wmma::accumulator, 16, 16, 8, float> acc[2];
        wmma::fill_fragment(acc[0], 0.0f);
        wmma::fill_fragment(acc[1], 0.0f);
#pragma unroll
        for (int kk = 0; kk < N_; kk += 8) {
            wmma::fragment<wmma::matrix_a, 16, 16, 8, wmma::precision::tf32, wmma::row_major> af;
            wmma::load_matrix_sync(af, &sS[warp * 16][kk], LS);
            to_tf32(af);
#pragma unroll
            for (int j = 0; j < 2; j++) {
                wmma::fragment<wmma::matrix_b, 16, 16, 8, wmma::precision::tf32, wmma::row_major> bf;
                wmma::load_matrix_sync(bf, &sV[kk][j * 16], LQ);
                to_tf32(bf);
                wmma::mma_sync(acc[j], af, bf, acc[j]);
            }
        }
        float* o = g_att + ((size_t)(wdw * N_ + warp * 16)) * DIM_ + h * HD_;
#pragma unroll
        for (int j = 0; j < 2; j++)
            wmma::store_matrix_sync(o + j * 16, acc[j], DIM_, wmma::mem_row_major);
    }
}

// ---------------------------------------------------------------------------
extern "C" void kernel_launch(void* const* d_in, const int* in_sizes, int n_in,
                              void* d_out, int out_size) {
    const float* x      = (const float*)d_in[0];
    const float* mask   = (const float*)d_in[1];
    const float* qkv_w  = (const float*)d_in[2];
    const float* qkv_b  = (const float*)d_in[3];
    const float* table  = (const float*)d_in[4];
    const float* proj_w = (const float*)d_in[5];
    const float* proj_b = (const float*)d_in[6];
    const int*   ridx   = (const int*)d_in[7];
    float* out = (float*)d_out;

    cudaFuncSetAttribute(qkv_kernel, cudaFuncAttributeMaxDynamicSharedMemorySize, GEMM_SMEM_BYTES);
    cudaFuncSetAttribute(proj_kernel, cudaFuncAttributeMaxDynamicSharedMemorySize, GEMM_SMEM_BYTES);

    // K0: expand rel-pos bias (tiny)
    bias_kernel<<<(NH_ * N_ * N_ + 255) / 256, 256>>>(table, ridx);
    // K1: QKV projection (65536 x 1536 x 512)
    qkv_kernel<<<dim3(TD3_ / BN, (BW_ * N_) / BM), 128, GEMM_SMEM_BYTES>>>(x, qkv_w, qkv_b);
    // K2: windowed attention
    attn_kernel<<<BW_ * NH_, 128>>>(mask);
    // K3: output projection (65536 x 512 x 512)
    proj_kernel<<<dim3(DIM_ / BN, (BW_ * N_) / BM), 128, GEMM_SMEM_BYTES>>>(proj_w, proj_b, out);
}

// round 10
// speedup vs baseline: 2.4463x; 1.0236x over previous
#include <cuda_runtime.h>
#include <cuda_bf16.h>
#include <mma.h>
#include <cstdint>

using namespace nvcuda;

// Problem constants
#define B_IMG   16
#define NW_     64
#define BW_     1024          // B_IMG * NW_
#define N_      64            // tokens per window
#define DIM_    512
#define NH_     16
#define HD_     32
#define TD3_    1536          // 3*DIM
#define SCALE_  0.17677669529663687f   // HD^-0.5

// Scratch
__device__ float g_qkv[3ull * BW_ * NH_ * N_ * HD_];   // tf32-rounded at store
__device__ float g_att[(size_t)BW_ * N_ * DIM_];       // tf32-rounded at store
__device__ float g_x[(size_t)BW_ * N_ * DIM_];         // tf32-rounded copy of x
__device__ float g_w1[TD3_ * DIM_];                    // tf32-rounded qkv_w
__device__ float g_w2[DIM_ * DIM_];                    // tf32-rounded proj_w
__device__ float g_bm[NW_ * NH_ * N_ * N_];            // rel-bias + shift-mask fused

#define QKV_STRIDE (1ull * BW_ * NH_ * N_ * HD_)

__device__ __forceinline__ float tf32r(float v) { return wmma::__float_to_tf32(v); }

// ---------------------------------------------------------------------------
// GEMM: 128x128 block tile, BK=32, 128 threads (4 warps, 64x64 per warp),
// 3-stage cp.async pipeline, operands pre-rounded to tf32 (no in-loop cvt),
// bias preloaded into accumulators, direct global fragment stores.
// ---------------------------------------------------------------------------
#define BM 128
#define BN 128
#define BK 32
#define LDT 36                        // stage row stride (32 + 4 pad)
#define STG_FLOATS ((BM + BN) * LDT)  // 9216 floats per stage
#define NSTAGE 3
#define LDBIAS 132
#define GEMM_SMEM_BYTES (NSTAGE * STG_FLOATS * 4)   // 110592 bytes

__device__ __forceinline__ void cp_async16(float* smem_dst, const float* gsrc) {
    unsigned int s = (unsigned int)__cvta_generic_to_shared(smem_dst);
    asm volatile("cp.async.cg.shared.global [%0], [%1], 16;\n" :: "r"(s), "l"(gsrc));
}
__device__ __forceinline__ void cp_commit() {
    asm volatile("cp.async.commit_group;\n" ::);
}
__device__ __forceinline__ void cp_wait1() {
    asm volatile("cp.async.wait_group 1;\n" ::);
}

template <typename FragT>
__device__ __forceinline__ void to_tf32(FragT& f) {
#pragma unroll
    for (int e = 0; e < f.num_elements; e++) f.x[e] = wmma::__float_to_tf32(f.x[e]);
}

// Issue one stage: A[BM][BK] from (m0, kt), B[BN][BK] from (j0, kt). 128 threads.
__device__ __forceinline__ void issue_stage(const float* __restrict__ A,
                                            const float* __restrict__ W,
                                            int K, int m0, int j0, int kt,
                                            float* stg, int tid) {
    float* sA = stg;
    float* sB = stg + BM * LDT;
#pragma unroll
    for (int u = 0; u < 8; u++) {
        int i = tid + u * 128;           // 1024 float4 for A
        int r = i >> 3, c4 = i & 7;
        cp_async16(&sA[r * LDT + c4 * 4], &A[(size_t)(m0 + r) * K + kt + c4 * 4]);
    }
#pragma unroll
    for (int u = 0; u < 8; u++) {
        int i = tid + u * 128;
        int r = i >> 3, c4 = i & 7;
        cp_async16(&sB[r * LDT + c4 * 4], &W[(size_t)(j0 + r) * K + kt + c4 * 4]);
    }
}

// Core: bias -> acc, 3-stage pipelined mainloop (no cvt: data pre-rounded).
__device__ __forceinline__ void gemm_core(const float* __restrict__ A,
                                          const float* __restrict__ W,
                                          const float* __restrict__ bias,
                                          int K, int m0, int j0,
                                          float* smem, int tid, int wm, int wn,
                                          wmma::fragment<wmma::accumulator, 16, 16, 8, float> (&acc)[4][4]) {
    // ---- bias preload (overlays stage 0 smem) ----
    for (int i = tid; i < 16 * BN; i += 128) {
        int r = i >> 7, c = i & 127;
        smem[r * LDBIAS + c] = bias[j0 + c];
    }
    __syncthreads();
#pragma unroll
    for (int j = 0; j < 4; j++) {
        wmma::load_matrix_sync(acc[0][j], &smem[wn * 64 + j * 16], LDBIAS, wmma::mem_row_major);
#pragma unroll
        for (int i = 1; i < 4; i++) acc[i][j] = acc[0][j];
    }
    __syncthreads();

    // ---- pipeline prologue: stages 0,1 ----
    const int T = K / BK;
    issue_stage(A, W, K, m0, j0, 0, smem, tid);
    cp_commit();
    issue_stage(A, W, K, m0, j0, BK, smem + STG_FLOATS, tid);
    cp_commit();

    int slot = 0;
    for (int t = 0; t < T; t++) {
        cp_wait1();
        __syncthreads();
        if (t + 2 < T) {
            issue_stage(A, W, K, m0, j0, (t + 2) * BK,
                        smem + ((slot + 2) % NSTAGE) * STG_FLOATS, tid);
        }
        cp_commit();

        float* sA = smem + slot * STG_FLOATS;
        float* sB = sA + BM * LDT;
#pragma unroll
        for (int kk = 0; kk < BK; kk += 8) {
            wmma::fragment<wmma::matrix_a, 16, 16, 8, wmma::precision::tf32, wmma::row_major> af[4];
            wmma::fragment<wmma::matrix_b, 16, 16, 8, wmma::precision::tf32, wmma::col_major> bf[4];
#pragma unroll
            for (int i = 0; i < 4; i++)
                wmma::load_matrix_sync(af[i], &sA[(wm * 64 + i * 16) * LDT + kk], LDT);
#pragma unroll
            for (int j = 0; j < 4; j++)
                wmma::load_matrix_sync(bf[j], &sB[(wn * 64 + j * 16) * LDT + kk], LDT);
#pragma unroll
            for (int i = 0; i < 4; i++)
#pragma unroll
                for (int j = 0; j < 4; j++)
                    wmma::mma_sync(acc[i][j], af[i], bf[j], acc[i][j]);
        }
        slot = (slot + 1) % NSTAGE;
    }
}

// K1: QKV projection; scatter to g_qkv (tf32-rounded); q pre-scaled.
extern "C" __global__ void __launch_bounds__(128)
qkv_kernel(const float* __restrict__ bias) {
    extern __shared__ float smem[];
    int tid  = threadIdx.x;
    int warp = tid >> 5;
    int wm   = warp & 1;
    int wn   = warp >> 1;

    int j0 = blockIdx.x * BN;
    int m0 = blockIdx.y * BM;
    int which = j0 >> 9;       // 0=q 1=k 2=v

    wmma::fragment<wmma::accumulator, 16, 16, 8, float> acc[4][4];
    gemm_core(g_x, g_w1, bias, DIM_, m0, j0, smem, tid, wm, wn, acc);

    float scale = (which == 0) ? SCALE_ : 1.0f;
#pragma unroll
    for (int i = 0; i < 4; i++)
#pragma unroll
        for (int j = 0; j < 4; j++) {
#pragma unroll
            for (int e = 0; e < acc[i][j].num_elements; e++)
                acc[i][j].x[e] = tf32r(acc[i][j].x[e] * scale);
            int row = m0 + wm * 64 + i * 16;
            int col = j0 + wn * 64 + j * 16;
            int wdw = row >> 6, n0 = row & 63;
            int h   = (col >> 5) & 15, d0 = col & 31;
            float* dst = g_qkv + (size_t)which * QKV_STRIDE
                       + ((size_t)(wdw * NH_ + h) * N_ + n0) * HD_ + d0;
            wmma::store_matrix_sync(dst, acc[i][j], HD_, wmma::mem_row_major);
        }
}

// K3: output projection
extern "C" __global__ void __launch_bounds__(128)
proj_kernel(const float* __restrict__ bias, float* __restrict__ out) {
    extern __shared__ float smem[];
    int tid  = threadIdx.x;
    int warp = tid >> 5;
    int wm   = warp & 1;
    int wn   = warp >> 1;

    int j0 = blockIdx.x * BN;
    int m0 = blockIdx.y * BM;

    wmma::fragment<wmma::accumulator, 16, 16, 8, float> acc[4][4];
    gemm_core(g_att, g_w2, bias, DIM_, m0, j0, smem, tid, wm, wn, acc);

#pragma unroll
    for (int i = 0; i < 4; i++)
#pragma unroll
        for (int j = 0; j < 4; j++) {
            int row = m0 + wm * 64 + i * 16;
            int col = j0 + wn * 64 + j * 16;
            wmma::store_matrix_sync(out + (size_t)row * DIM_ + col, acc[i][j],
                                    DIM_, wmma::mem_row_major);
        }
}

// ---------------------------------------------------------------------------
// Pre-pass kernels
// ---------------------------------------------------------------------------
// tf32-round x into g_x (float4 vectorized)
extern "C" __global__ void __launch_bounds__(256)
cvt_x_kernel(const float* __restrict__ x) {
    size_t i = ((size_t)blockIdx.x * 256 + threadIdx.x) * 4;
    float4 v = *(const float4*)(x + i);
    v.x = tf32r(v.x); v.y = tf32r(v.y); v.z = tf32r(v.z); v.w = tf32r(v.w);
    *(float4*)(g_x + i) = v;
}

// tf32-round both weight matrices (qkv_w then proj_w)
extern "C" __global__ void __launch_bounds__(256)
cvt_w_kernel(const float* __restrict__ w1, const float* __restrict__ w2) {
    size_t i = ((size_t)blockIdx.x * 256 + threadIdx.x) * 4;
    const size_t n1 = (size_t)TD3_ * DIM_;
    if (i < n1) {
        float4 v = *(const float4*)(w1 + i);
        v.x = tf32r(v.x); v.y = tf32r(v.y); v.z = tf32r(v.z); v.w = tf32r(v.w);
        *(float4*)(g_w1 + i) = v;
    } else {
        size_t j = i - n1;
        float4 v = *(const float4*)(w2 + j);
        v.x = tf32r(v.x); v.y = tf32r(v.y); v.z = tf32r(v.z); v.w = tf32r(v.w);
        *(float4*)(g_w2 + j) = v;
    }
}

// fuse rel-pos bias (per head) + shift mask (per window) -> g_bm[w][h][r*64+c]
extern "C" __global__ void __launch_bounds__(256)
bm_kernel(const float* __restrict__ table, const int* __restrict__ ridx,
          const float* __restrict__ mask) {
    int i = blockIdx.x * 256 + threadIdx.x;      // 0 .. NW*NH*4096-1
    int rc = i & 4095;
    int h  = (i >> 12) & 15;
    int w  = i >> 16;
    g_bm[i] = table[ridx[rc] * NH_ + h] + mask[w * 4096 + rc];
}

// ---------------------------------------------------------------------------
// K2: attention per (window, head). 128 threads (4 warps).
// ---------------------------------------------------------------------------
#define LQ 36
#define LS 68

extern "C" __global__ void __launch_bounds__(128)
attn_kernel() {
    __shared__ float sQ[N_][LQ];
    __shared__ float sK[N_][LQ];
    __shared__ float sV[N_][LQ];
    __shared__ float sS[N_][LS];

    int bwh = blockIdx.x;
    int wdw = bwh >> 4;
    int h   = bwh & 15;
    int tid = threadIdx.x;
    int warp = tid >> 5;

    const float* q = g_qkv + (size_t)bwh * (N_ * HD_);
    const float* k = q + QKV_STRIDE;
    const float* v = k + QKV_STRIDE;

    for (int i = tid; i < 512; i += 128) {
        int n = i >> 3, c4 = i & 7;
        *(float4*)&sQ[n][c4 * 4] = *(const float4*)&q[n * HD_ + c4 * 4];
        *(float4*)&sK[n][c4 * 4] = *(const float4*)&k[n * HD_ + c4 * 4];
        *(float4*)&sV[n][c4 * 4] = *(const float4*)&v[n * HD_ + c4 * 4];
    }
    __syncthreads();

    // scores: S = Qs @ K^T  (operands pre-rounded, no cvt)
    {
        wmma::fragment<wmma::accumulator, 16, 16, 8, float> acc[4];
#pragma unroll
        for (int j = 0; j < 4; j++) wmma::fill_fragment(acc[j], 0.0f);
#pragma unroll
        for (int kk = 0; kk < HD_; kk += 8) {
            wmma::fragment<wmma::matrix_a, 16, 16, 8, wmma::precision::tf32, wmma::row_major> af;
            wmma::load_matrix_sync(af, &sQ[warp * 16][kk], LQ);
#pragma unroll
            for (int j = 0; j < 4; j++) {
                wmma::fragment<wmma::matrix_b, 16, 16, 8, wmma::precision::tf32, wmma::col_major> bf;
                wmma::load_matrix_sync(bf, &sK[j * 16][kk], LQ);
                wmma::mma_sync(acc[j], af, bf, acc[j]);
            }
        }
#pragma unroll
        for (int j = 0; j < 4; j++)
            wmma::store_matrix_sync(&sS[warp * 16][j * 16], acc[j], LS, wmma::mem_row_major);
    }
    __syncthreads();

    // fused bias+mask + softmax: 2 threads per row, 32 cols each
    {
        int r    = tid >> 1;
        int base = (tid & 1) * 32;
        const float4* bmrow = (const float4*)(g_bm
            + (((size_t)(wdw & 63) * NH_ + h) * N_ + r) * N_ + base);

        float vals[32];
        float mx = -1e30f;
#pragma unroll
        for (int c4 = 0; c4 < 8; c4++) {
            float4 bm = bmrow[c4];
            float* vp = vals + c4 * 4;
            vp[0] = sS[r][base + c4 * 4 + 0] + bm.x;
            vp[1] = sS[r][base + c4 * 4 + 1] + bm.y;
            vp[2] = sS[r][base + c4 * 4 + 2] + bm.z;
            vp[3] = sS[r][base + c4 * 4 + 3] + bm.w;
            mx = fmaxf(mx, fmaxf(fmaxf(vp[0], vp[1]), fmaxf(vp[2], vp[3])));
        }
        mx = fmaxf(mx, __shfl_xor_sync(0xffffffffu, mx, 1));
        float sum = 0.0f;
#pragma unroll
        for (int c = 0; c < 32; c++) {
            float e = __expf(vals[c] - mx);
            vals[c] = e;
            sum += e;
        }
        sum += __shfl_xor_sync(0xffffffffu, sum, 1);
        float inv = 1.0f / sum;
#pragma unroll
        for (int c = 0; c < 32; c++) sS[r][base + c] = vals[c] * inv;
    }
    __syncthreads();

    // O = P @ V  (V pre-rounded; P needs rounding)
    {
        wmma::fragment<wmma::accumulator, 16, 16, 8, float> acc[2];
        wmma::fill_fragment(acc[0], 0.0f);
        wmma::fill_fragment(acc[1], 0.0f);
#pragma unroll
        for (int kk = 0; kk < N_; kk += 8) {
            wmma::fragment<wmma::matrix_a, 16, 16, 8, wmma::precision::tf32, wmma::row_major> af;
            wmma::load_matrix_sync(af, &sS[warp * 16][kk], LS);
            to_tf32(af);
#pragma unroll
            for (int j = 0; j < 2; j++) {
                wmma::fragment<wmma::matrix_b, 16, 16, 8, wmma::precision::tf32, wmma::row_major> bf;
                wmma::load_matrix_sync(bf, &sV[kk][j * 16], LQ);
                wmma::mma_sync(acc[j], af, bf, acc[j]);
            }
        }
        // store tf32-rounded (feeds K3's MMA A operand)
#pragma unroll
        for (int j = 0; j < 2; j++) {
#pragma unroll
            for (int e = 0; e < acc[j].num_elements; e++) acc[j].x[e] = tf32r(acc[j].x[e]);
            float* o = g_att + ((size_t)(wdw * N_ + warp * 16)) * DIM_ + h * HD_;
            wmma::store_matrix_sync(o + j * 16, acc[j], DIM_, wmma::mem_row_major);
        }
    }
}

// ---------------------------------------------------------------------------
extern "C" void kernel_launch(void* const* d_in, const int* in_sizes, int n_in,
                              void* d_out, int out_size) {
    const float* x      = (const float*)d_in[0];
    const float* mask   = (const float*)d_in[1];
    const float* qkv_w  = (const float*)d_in[2];
    const float* qkv_b  = (const float*)d_in[3];
    const float* table  = (const float*)d_in[4];
    const float* proj_w = (const float*)d_in[5];
    const float* proj_b = (const float*)d_in[6];
    const int*   ridx   = (const int*)d_in[7];
    float* out = (float*)d_out;

    cudaFuncSetAttribute(qkv_kernel, cudaFuncAttributeMaxDynamicSharedMemorySize, GEMM_SMEM_BYTES);
    cudaFuncSetAttribute(proj_kernel, cudaFuncAttributeMaxDynamicSharedMemorySize, GEMM_SMEM_BYTES);

    // Pre-passes (independent; cheap)
    cvt_x_kernel<<<((size_t)BW_ * N_ * DIM_ / 4) / 256, 256>>>(x);
    cvt_w_kernel<<<((TD3_ + DIM_) * DIM_ / 4) / 256, 256>>>(qkv_w, proj_w);
    bm_kernel<<<NW_ * NH_ * N_ * N_ / 256, 256>>>(table, ridx, mask);

    // K1: QKV projection (65536 x 1536 x 512)
    qkv_kernel<<<dim3(TD3_ / BN, (BW_ * N_) / BM), 128, GEMM_SMEM_BYTES>>>(qkv_b);
    // K2: windowed attention
    attn_kernel<<<BW_ * NH_, 128>>>();
    // K3: output projection (65536 x 512 x 512)
    proj_kernel<<<dim3(DIM_ / BN, (BW_ * N_) / BM), 128, GEMM_SMEM_BYTES>>>(proj_b, out);
}